// round 2
// baseline (speedup 1.0000x reference)
#include <cuda_runtime.h>

#define NV   2562
#define DEG  8
#define FIN  8
#define FOUT 16
#define KCH  5
#define SP   512                 // spatial = X*Y*Z
#define SP2  (SP/2)              // 256 float2 per (v,f) row-chunk
#define DD   (FIN*SP)            // 4096 floats per vertex row
#define DD2  (DD/2)              // 2048 float2

// Scratch: 3 rolling Chebyshev levels (x1, x2, x3), 42 MB each.
__device__ float2 g_buf[3][(size_t)NV * DD2];

// One block per vertex v; 256 threads cover the 512 spatial floats as float2.
// x_next[v,f,s] = (has_prev ? 2*spmv - prev : spmv)
__global__ __launch_bounds__(SP2) void spmv_step_kernel(
    const float2* __restrict__ cur,  int cvs2, int cfs2,   // strides in float2 units
    const float2* __restrict__ prev, int pvs2, int pfs2,
    float2* __restrict__ next,
    const int* __restrict__ cols, const float* __restrict__ vals,
    int has_prev)
{
    __shared__ int   scol[DEG];
    __shared__ float sval[DEG];
    const int v = blockIdx.x;
    const int t = threadIdx.x;
    if (t < DEG) {
        scol[t] = cols[v * DEG + t];
        sval[t] = vals[v * DEG + t];
    }
    __syncthreads();

    #pragma unroll
    for (int f = 0; f < FIN; ++f) {
        float2 acc = make_float2(0.f, 0.f);
        #pragma unroll
        for (int n = 0; n < DEG; ++n) {
            const float2 x = cur[(size_t)scol[n] * cvs2 + f * cfs2 + t];
            const float  w = sval[n];
            acc.x += w * x.x; acc.y += w * x.y;
        }
        if (has_prev) {
            const float2 p = prev[(size_t)v * pvs2 + f * pfs2 + t];
            acc.x = 2.f * acc.x - p.x;
            acc.y = 2.f * acc.y - p.y;
        }
        next[(size_t)v * DD2 + f * SP2 + t] = acc;
    }
}

// Last SpMV (x4) fused with the (K,FIN)->(FOUT) contraction + bias.
// x0 = inputs (native [f,v,s] layout), x1..x3 in scratch ([v,f,s] layout).
__global__ __launch_bounds__(SP2) void final_kernel(
    const float2* __restrict__ x0,
    const float2* __restrict__ x1,
    const float2* __restrict__ x2,
    const float2* __restrict__ x3,
    const int* __restrict__ cols, const float* __restrict__ vals,
    const float* __restrict__ weight, const float* __restrict__ bias,
    float2* __restrict__ out)
{
    __shared__ int   scol[DEG];
    __shared__ float sval[DEG];
    __shared__ float sw[KCH * FIN * FOUT];   // 640 floats, [k][f][o]
    __shared__ float sb[FOUT];

    const int v = blockIdx.x;
    const int t = threadIdx.x;
    if (t < DEG) {
        scol[t] = cols[v * DEG + t];
        sval[t] = vals[v * DEG + t];
    }
    for (int i = t; i < KCH * FIN * FOUT; i += blockDim.x) sw[i] = weight[i];
    if (t < FOUT) sb[t] = bias[t];
    __syncthreads();

    float2 c[FOUT];
    #pragma unroll
    for (int o = 0; o < FOUT; ++o)
        c[o] = make_float2(sb[o], sb[o]);

    #pragma unroll
    for (int f = 0; f < FIN; ++f) {
        // x4[v,f,s] = 2 * spmv(x3) - x2
        float2 acc = make_float2(0.f, 0.f);
        #pragma unroll
        for (int n = 0; n < DEG; ++n) {
            const float2 x = x3[(size_t)scol[n] * DD2 + f * SP2 + t];
            const float  w = sval[n];
            acc.x += w * x.x; acc.y += w * x.y;
        }
        const float2 p2 = x2[(size_t)v * DD2 + f * SP2 + t];
        float2 x4f;
        x4f.x = 2.f * acc.x - p2.x;
        x4f.y = 2.f * acc.y - p2.y;

        const float2 x0f = x0[(size_t)f * (NV * SP2) + (size_t)v * SP2 + t];
        const float2 x1f = x1[(size_t)v * DD2 + f * SP2 + t];
        const float2 x3f = x3[(size_t)v * DD2 + f * SP2 + t];

        #pragma unroll
        for (int o = 0; o < FOUT; ++o) {
            const float w0 = sw[0 * FIN * FOUT + f * FOUT + o];
            const float w1 = sw[1 * FIN * FOUT + f * FOUT + o];
            const float w2 = sw[2 * FIN * FOUT + f * FOUT + o];
            const float w3 = sw[3 * FIN * FOUT + f * FOUT + o];
            const float w4 = sw[4 * FIN * FOUT + f * FOUT + o];
            c[o].x += x0f.x*w0 + x1f.x*w1 + p2.x*w2 + x3f.x*w3 + x4f.x*w4;
            c[o].y += x0f.y*w0 + x1f.y*w1 + p2.y*w2 + x3f.y*w3 + x4f.y*w4;
        }
    }

    #pragma unroll
    for (int o = 0; o < FOUT; ++o)
        out[(size_t)o * (NV * SP2) + (size_t)v * SP2 + t] = c[o];
}

extern "C" void kernel_launch(void* const* d_in, const int* in_sizes, int n_in,
                              void* d_out, int out_size) {
    const float* inputs = (const float*)d_in[0];
    // d_in[1] = lap_rows (unused: rows are repeat(arange(V), DEG) by construction)
    const int*   cols   = (const int*)d_in[2];
    const float* vals   = (const float*)d_in[3];
    const float* weight = (const float*)d_in[4];
    const float* bias   = (const float*)d_in[5];
    float2*      out    = (float2*)d_out;

    void* sym = nullptr;
    cudaGetSymbolAddress(&sym, g_buf);
    float2* g0 = (float2*)sym;
    float2* g1 = g0 + (size_t)NV * DD2;
    float2* g2 = g1 + (size_t)NV * DD2;

    const float2* in2 = (const float2*)inputs;
    const int IVS2 = SP2;            // input vertex stride (float2)
    const int IFS2 = NV * SP2;       // input feature stride (float2)

    // x1 = L @ x0 (x0 read directly from inputs layout)
    spmv_step_kernel<<<NV, SP2>>>(in2, IVS2, IFS2, nullptr, 0, 0,
                                  g0, cols, vals, 0);
    // x2 = 2 L x1 - x0
    spmv_step_kernel<<<NV, SP2>>>(g0, DD2, SP2, in2, IVS2, IFS2,
                                  g1, cols, vals, 1);
    // x3 = 2 L x2 - x1
    spmv_step_kernel<<<NV, SP2>>>(g1, DD2, SP2, g0, DD2, SP2,
                                  g2, cols, vals, 1);
    // x4 (in registers) + einsum over (k,f) + bias -> out
    final_kernel<<<NV, SP2>>>(in2, g0, g1, g2, cols, vals, weight, bias, out);
}

// round 3
// speedup vs baseline: 1.3793x; 1.3793x over previous
#include <cuda_runtime.h>

#define NV   2562
#define DEG  8
#define FIN  8
#define FOUT 16
#define KCH  5
#define SP   512                 // spatial = X*Y*Z
#define SP4  (SP/4)              // 128 float4 per (v,f) row-chunk
#define DD   (FIN*SP)            // 4096 floats per vertex row
#define DD4  (DD/4)              // 1024 float4

// Scratch: 3 rolling Chebyshev levels (x1, x2, x3), 42 MB each.
__device__ float4 g_buf[3][(size_t)NV * DD4];

// One block per vertex v; 128 threads cover the 512 spatial floats as float4.
// x_next[v,f,s] = (has_prev ? 2*spmv - prev : spmv)
__global__ __launch_bounds__(SP4) void spmv_step_kernel(
    const float4* __restrict__ cur,  int cvs4, int cfs4,   // strides in float4 units
    const float4* __restrict__ prev, int pvs4, int pfs4,
    float4* __restrict__ next,
    const int* __restrict__ cols, const float* __restrict__ vals,
    int has_prev)
{
    __shared__ int   scol[DEG];
    __shared__ float sval[DEG];
    const int v = blockIdx.x;
    const int t = threadIdx.x;
    if (t < DEG) {
        scol[t] = cols[v * DEG + t];
        sval[t] = vals[v * DEG + t];
    }
    __syncthreads();

    #pragma unroll
    for (int f = 0; f < FIN; ++f) {
        float4 acc = make_float4(0.f, 0.f, 0.f, 0.f);
        #pragma unroll
        for (int n = 0; n < DEG; ++n) {
            const float4 x = cur[(size_t)scol[n] * cvs4 + f * cfs4 + t];
            const float  w = sval[n];
            acc.x += w * x.x; acc.y += w * x.y;
            acc.z += w * x.z; acc.w += w * x.w;
        }
        if (has_prev) {
            const float4 p = prev[(size_t)v * pvs4 + f * pfs4 + t];
            acc.x = 2.f * acc.x - p.x; acc.y = 2.f * acc.y - p.y;
            acc.z = 2.f * acc.z - p.z; acc.w = 2.f * acc.w - p.w;
        }
        next[(size_t)v * DD4 + f * SP4 + t] = acc;
    }
}

// Final: compute x4 row cooperatively into smem (one gather), then split the
// FOUT=16 outputs across two 128-thread o-groups so each thread carries only
// 8 float4 accumulators. __launch_bounds__(256,2) -> 16 warps/SM.
__global__ __launch_bounds__(2 * SP4, 2) void final_kernel(
    const float4* __restrict__ x0,
    const float4* __restrict__ x1,
    const float4* __restrict__ x2,
    const float4* __restrict__ x3,
    const int* __restrict__ cols, const float* __restrict__ vals,
    const float* __restrict__ weight, const float* __restrict__ bias,
    float4* __restrict__ out)
{
    __shared__ int    scol[DEG];
    __shared__ float  sval[DEG];
    __shared__ float  sw[KCH * FIN * FOUT];   // 640 floats, [k][f][o]
    __shared__ float  sb[FOUT];
    __shared__ float4 sx4[FIN * SP4];         // 16 KB: x4 row for this vertex

    const int v   = blockIdx.x;
    const int tid = threadIdx.x;

    if (tid < DEG) {
        scol[tid] = cols[v * DEG + tid];
        sval[tid] = vals[v * DEG + tid];
    }
    for (int i = tid; i < KCH * FIN * FOUT; i += blockDim.x) sw[i] = weight[i];
    if (tid < FOUT) sb[tid] = bias[tid];
    __syncthreads();

    // Phase 1: all 256 threads compute x4[v, f, t] = 2*spmv(x3) - x2 into smem.
    #pragma unroll
    for (int j = 0; j < (FIN * SP4) / (2 * SP4); ++j) {   // 4 iterations
        const int idx = tid + j * (2 * SP4);
        const int f   = idx >> 7;          // /128
        const int t   = idx & (SP4 - 1);
        float4 acc = make_float4(0.f, 0.f, 0.f, 0.f);
        #pragma unroll
        for (int n = 0; n < DEG; ++n) {
            const float4 x = x3[(size_t)scol[n] * DD4 + f * SP4 + t];
            const float  w = sval[n];
            acc.x += w * x.x; acc.y += w * x.y;
            acc.z += w * x.z; acc.w += w * x.w;
        }
        const float4 p2 = x2[(size_t)v * DD4 + f * SP4 + t];
        acc.x = 2.f * acc.x - p2.x; acc.y = 2.f * acc.y - p2.y;
        acc.z = 2.f * acc.z - p2.z; acc.w = 2.f * acc.w - p2.w;
        sx4[idx] = acc;
    }
    __syncthreads();

    // Phase 2: o-group split. Threads [0,128) -> o=0..7, [128,256) -> o=8..15.
    const int half   = tid >> 7;           // 0 or 1
    const int o_base = half * (FOUT / 2);
    const int t      = tid & (SP4 - 1);

    float4 c[FOUT / 2];
    #pragma unroll
    for (int oo = 0; oo < FOUT / 2; ++oo) {
        const float b = sb[o_base + oo];
        c[oo] = make_float4(b, b, b, b);
    }

    #pragma unroll
    for (int f = 0; f < FIN; ++f) {
        const float4 x0f = x0[(size_t)f * (NV * SP4) + (size_t)v * SP4 + t];
        const float4 x1f = x1[(size_t)v * DD4 + f * SP4 + t];
        const float4 x2f = x2[(size_t)v * DD4 + f * SP4 + t];
        const float4 x3f = x3[(size_t)v * DD4 + f * SP4 + t];
        const float4 x4f = sx4[f * SP4 + t];

        #pragma unroll
        for (int oo = 0; oo < FOUT / 2; ++oo) {
            const int o = o_base + oo;
            const float w0 = sw[0 * FIN * FOUT + f * FOUT + o];
            const float w1 = sw[1 * FIN * FOUT + f * FOUT + o];
            const float w2 = sw[2 * FIN * FOUT + f * FOUT + o];
            const float w3 = sw[3 * FIN * FOUT + f * FOUT + o];
            const float w4 = sw[4 * FIN * FOUT + f * FOUT + o];
            c[oo].x += x0f.x*w0 + x1f.x*w1 + x2f.x*w2 + x3f.x*w3 + x4f.x*w4;
            c[oo].y += x0f.y*w0 + x1f.y*w1 + x2f.y*w2 + x3f.y*w3 + x4f.y*w4;
            c[oo].z += x0f.z*w0 + x1f.z*w1 + x2f.z*w2 + x3f.z*w3 + x4f.z*w4;
            c[oo].w += x0f.w*w0 + x1f.w*w1 + x2f.w*w2 + x3f.w*w3 + x4f.w*w4;
        }
    }

    #pragma unroll
    for (int oo = 0; oo < FOUT / 2; ++oo)
        out[(size_t)(o_base + oo) * (NV * SP4) + (size_t)v * SP4 + t] = c[oo];
}

extern "C" void kernel_launch(void* const* d_in, const int* in_sizes, int n_in,
                              void* d_out, int out_size) {
    const float* inputs = (const float*)d_in[0];
    // d_in[1] = lap_rows (unused: rows are repeat(arange(V), DEG) by construction)
    const int*   cols   = (const int*)d_in[2];
    const float* vals   = (const float*)d_in[3];
    const float* weight = (const float*)d_in[4];
    const float* bias   = (const float*)d_in[5];
    float4*      out    = (float4*)d_out;

    void* sym = nullptr;
    cudaGetSymbolAddress(&sym, g_buf);
    float4* g0 = (float4*)sym;
    float4* g1 = g0 + (size_t)NV * DD4;
    float4* g2 = g1 + (size_t)NV * DD4;

    const float4* in4 = (const float4*)inputs;
    const int IVS4 = SP4;            // input vertex stride (float4)
    const int IFS4 = NV * SP4;       // input feature stride (float4)

    // x1 = L @ x0 (x0 read directly from inputs layout)
    spmv_step_kernel<<<NV, SP4>>>(in4, IVS4, IFS4, nullptr, 0, 0,
                                  g0, cols, vals, 0);
    // x2 = 2 L x1 - x0
    spmv_step_kernel<<<NV, SP4>>>(g0, DD4, SP4, in4, IVS4, IFS4,
                                  g1, cols, vals, 1);
    // x3 = 2 L x2 - x1
    spmv_step_kernel<<<NV, SP4>>>(g1, DD4, SP4, g0, DD4, SP4,
                                  g2, cols, vals, 1);
    // x4 (smem) + einsum over (k,f) + bias -> out, o-split across the block
    final_kernel<<<NV, 2 * SP4>>>(in4, g0, g1, g2, cols, vals, weight, bias, out);
}